// round 3
// baseline (speedup 1.0000x reference)
#include <cuda_runtime.h>
#include <cstdint>

#define D     128
#define LDIM  64
#define NMAX  50000
#define EMAX  625000
#define EPS   1e-5f
#define SLOPE 0.01f

// ---------------- scratch (static device globals; no allocation) ----------------
__device__ float g_h  [NMAX * D];
__device__ float g_agg[NMAX * D];
__device__ float g_x1 [NMAX * D];
__device__ float g_x2 [NMAX * D];
__device__ float g_dinv[NMAX];
__device__ int   g_counts[NMAX];
__device__ int   g_rowptr[NMAX + 1];
__device__ int   g_wofs[NMAX];
__device__ int   g_col[EMAX];
__device__ float g_stats[2 * D];
__device__ float g_Wcat[D * D];
__device__ float g_bcat[D];

// ---------------- graph preprocessing ----------------
__global__ void k_zero_counts(int* counts, int n) {
    int i = blockIdx.x * blockDim.x + threadIdx.x;
    if (i < n) counts[i] = 0;
}

__global__ void k_count(const int* __restrict__ dst, int* counts, int e) {
    int i = blockIdx.x * blockDim.x + threadIdx.x;
    if (i < e) atomicAdd(&counts[dst[i]], 1);
}

// single-block scan over up to NMAX counts -> exclusive rowptr
__global__ void k_scan(const int* __restrict__ counts, int* rowptr, int n) {
    __shared__ int sh[1024];
    __shared__ int carry;
    int tid = threadIdx.x;
    if (tid == 0) { carry = 0; rowptr[0] = 0; }
    __syncthreads();
    for (int base = 0; base < n; base += 1024) {
        int i = base + tid;
        int v = (i < n) ? counts[i] : 0;
        sh[tid] = v;
        __syncthreads();
        for (int off = 1; off < 1024; off <<= 1) {
            int t = (tid >= off) ? sh[tid - off] : 0;
            __syncthreads();
            sh[tid] += t;
            __syncthreads();
        }
        int cb = carry;
        if (i < n) rowptr[i + 1] = cb + sh[tid];
        __syncthreads();
        if (tid == 0) carry = cb + sh[1023];
        __syncthreads();
    }
}

__global__ void k_aux(const int* __restrict__ rowptr, const int* __restrict__ counts,
                      int* wofs, float* dinv, int n) {
    int i = blockIdx.x * blockDim.x + threadIdx.x;
    if (i < n) {
        wofs[i] = rowptr[i];
        dinv[i] = rsqrtf((float)(counts[i] + 1));  // +1 self-loop
    }
}

__global__ void k_fill(const int* __restrict__ src, const int* __restrict__ dst,
                       int* wofs, int* col, int e) {
    int i = blockIdx.x * blockDim.x + threadIdx.x;
    if (i < e) {
        int d = dst[i];
        int pos = atomicAdd(&wofs[d], 1);
        col[pos] = src[i];
    }
}

__global__ void k_pack(const float* __restrict__ Wmu, const float* __restrict__ Wlv,
                       const float* __restrict__ bmu, const float* __restrict__ blv,
                       float* Wcat, float* bcat) {
    int i = blockIdx.x * blockDim.x + threadIdx.x;
    if (i < D * D) {
        int k = i >> 7, c = i & 127;
        Wcat[i] = (c < LDIM) ? Wmu[k * LDIM + c] : Wlv[k * LDIM + (c - LDIM)];
    }
    if (i < D) bcat[i] = (i < LDIM) ? bmu[i] : blv[i - LDIM];
}

// ---------------- GEMM: C[M,128] = A[M,128] @ B[128,128] ----------------
__global__ __launch_bounds__(256) void k_gemm(const float* __restrict__ A,
                                              const float* __restrict__ B,
                                              float* __restrict__ C, int M) {
    __shared__ float As[16][64];
    __shared__ float Bs[16][128];
    const int tx = threadIdx.x & 15;   // 0..15  -> 8 output cols each
    const int ty = threadIdx.x >> 4;   // 0..15  -> 4 output rows each
    const int row0 = blockIdx.x * 64;

    float acc[4][8];
    #pragma unroll
    for (int m = 0; m < 4; m++)
        #pragma unroll
        for (int nn = 0; nn < 8; nn++) acc[m][nn] = 0.f;

    for (int k0 = 0; k0 < D; k0 += 16) {
        #pragma unroll
        for (int i = threadIdx.x; i < 64 * 16; i += 256) {
            int r = i >> 4, c = i & 15;
            int gr = row0 + r;
            As[c][r] = (gr < M) ? A[gr * D + k0 + c] : 0.f;
        }
        #pragma unroll
        for (int i = threadIdx.x; i < 16 * 128; i += 256) {
            int r = i >> 7, c = i & 127;
            Bs[r][c] = B[(k0 + r) * D + c];
        }
        __syncthreads();
        #pragma unroll
        for (int k = 0; k < 16; k++) {
            float a[4], b[8];
            *(float4*)a       = *(const float4*)&As[k][ty * 4];
            *(float4*)b       = *(const float4*)&Bs[k][tx * 8];
            *(float4*)(b + 4) = *(const float4*)&Bs[k][tx * 8 + 4];
            #pragma unroll
            for (int m = 0; m < 4; m++)
                #pragma unroll
                for (int nn = 0; nn < 8; nn++)
                    acc[m][nn] = fmaf(a[m], b[nn], acc[m][nn]);
        }
        __syncthreads();
    }
    #pragma unroll
    for (int m = 0; m < 4; m++) {
        int gr = row0 + ty * 4 + m;
        if (gr < M) {
            float4 v0 = make_float4(acc[m][0], acc[m][1], acc[m][2], acc[m][3]);
            float4 v1 = make_float4(acc[m][4], acc[m][5], acc[m][6], acc[m][7]);
            *(float4*)&C[gr * D + tx * 8]     = v0;
            *(float4*)&C[gr * D + tx * 8 + 4] = v1;
        }
    }
}

// ---------------- propagation: out[d] = dinv[d]*(sum dinv[s]h[s] + dinv[d]h[d]) + b ----------------
template <bool SPLIT>
__global__ __launch_bounds__(256) void k_prop(const float4* __restrict__ h4,
                                              const float* __restrict__ dinv,
                                              const int* __restrict__ rowptr,
                                              const int* __restrict__ col,
                                              const float* __restrict__ bias,
                                              float4* __restrict__ out_a,
                                              float4* __restrict__ out_b, int n) {
    int w = (blockIdx.x * blockDim.x + threadIdx.x) >> 5;
    int lane = threadIdx.x & 31;
    if (w >= n) return;
    float dd = dinv[w];
    float4 v = h4[w * 32 + lane];
    float4 acc;
    acc.x = dd * v.x; acc.y = dd * v.y; acc.z = dd * v.z; acc.w = dd * v.w;
    int beg = rowptr[w], end = rowptr[w + 1];
    for (int e = beg; e < end; e++) {
        int s = col[e];
        float ds = dinv[s];
        float4 u = h4[s * 32 + lane];
        acc.x = fmaf(ds, u.x, acc.x);
        acc.y = fmaf(ds, u.y, acc.y);
        acc.z = fmaf(ds, u.z, acc.z);
        acc.w = fmaf(ds, u.w, acc.w);
    }
    const float4 b4 = *(const float4*)(bias + lane * 4);
    acc.x = fmaf(acc.x, dd, b4.x);
    acc.y = fmaf(acc.y, dd, b4.y);
    acc.z = fmaf(acc.z, dd, b4.z);
    acc.w = fmaf(acc.w, dd, b4.w);
    if (!SPLIT) {
        out_a[w * 32 + lane] = acc;
    } else {
        if (lane < 16) out_a[w * 16 + lane]        = acc;  // mu
        else           out_b[w * 16 + (lane - 16)] = acc;  // logvar
    }
}

// ---------------- batchnorm ----------------
__global__ void k_zero_stats(float* stats) {
    stats[threadIdx.x] = 0.f;  // 256 threads
}

__global__ __launch_bounds__(256) void k_bnstats(const float* __restrict__ x,
                                                 float* stats, int n) {
    const int c = threadIdx.x & 127;
    const int half = threadIdx.x >> 7;
    const int r0 = blockIdx.x * 64;
    const int rend = min(r0 + 64, n);
    float s = 0.f, q = 0.f;
    for (int r = r0 + half; r < rend; r += 2) {
        float v = x[r * D + c];
        s += v; q += v * v;
    }
    __shared__ float sh[256], shq[256];
    sh[threadIdx.x] = s; shq[threadIdx.x] = q;
    __syncthreads();
    if (half == 0) {
        atomicAdd(&stats[c],     s + sh[threadIdx.x + 128]);
        atomicAdd(&stats[D + c], q + shq[threadIdx.x + 128]);
    }
}

__global__ __launch_bounds__(256) void k_bnapply(const float4* __restrict__ agg,
                                                 const float* __restrict__ stats,
                                                 const float* __restrict__ gamma,
                                                 const float* __restrict__ beta,
                                                 const float4* __restrict__ xres,
                                                 float4* __restrict__ xout, int n) {
    int idx = blockIdx.x * blockDim.x + threadIdx.x;
    int total = n * 32;
    if (idx >= total) return;
    int c = (idx & 31) * 4;
    float inv_n = 1.f / (float)n;
    float sc[4], sf[4];
    #pragma unroll
    for (int j = 0; j < 4; j++) {
        float mean = stats[c + j] * inv_n;
        float var  = stats[D + c + j] * inv_n - mean * mean;
        float s = gamma[c + j] * rsqrtf(var + EPS);
        sc[j] = s;
        sf[j] = beta[c + j] - mean * s;
    }
    float4 v = agg[idx];
    float4 r = xres[idx];
    float y0 = fmaf(v.x, sc[0], sf[0]);
    float y1 = fmaf(v.y, sc[1], sf[1]);
    float y2 = fmaf(v.z, sc[2], sf[2]);
    float y3 = fmaf(v.w, sc[3], sf[3]);
    y0 = (y0 >= 0.f) ? y0 : SLOPE * y0;
    y1 = (y1 >= 0.f) ? y1 : SLOPE * y1;
    y2 = (y2 >= 0.f) ? y2 : SLOPE * y2;
    y3 = (y3 >= 0.f) ? y3 : SLOPE * y3;
    float4 o = make_float4(y0 + r.x, y1 + r.y, y2 + r.z, y3 + r.w);
    xout[idx] = o;
}

// ---------------- launcher ----------------
extern "C" void kernel_launch(void* const* d_in, const int* in_sizes, int n_in,
                              void* d_out, int out_size) {
    const float* x     = (const float*)d_in[0];
    const int*   ei    = (const int*)d_in[1];     // int32! (jax x64 disabled)
    const float* Ws    = (const float*)d_in[2];
    const float* bs    = (const float*)d_in[3];
    const float* Wmu   = (const float*)d_in[4];
    const float* bmu   = (const float*)d_in[5];
    const float* Wlv   = (const float*)d_in[6];
    const float* blv   = (const float*)d_in[7];
    const float* gamma = (const float*)d_in[8];
    const float* beta  = (const float*)d_in[9];

    const int n = in_sizes[0] / D;
    const int e = in_sizes[1] / 2;
    float* out = (float*)d_out;

    float *h, *agg, *x1, *x2, *dinv, *stats, *Wcat, *bcat;
    int *counts, *rowptr, *wofs, *col;
    cudaGetSymbolAddress((void**)&h,      g_h);
    cudaGetSymbolAddress((void**)&agg,    g_agg);
    cudaGetSymbolAddress((void**)&x1,     g_x1);
    cudaGetSymbolAddress((void**)&x2,     g_x2);
    cudaGetSymbolAddress((void**)&dinv,   g_dinv);
    cudaGetSymbolAddress((void**)&stats,  g_stats);
    cudaGetSymbolAddress((void**)&Wcat,   g_Wcat);
    cudaGetSymbolAddress((void**)&bcat,   g_bcat);
    cudaGetSymbolAddress((void**)&counts, g_counts);
    cudaGetSymbolAddress((void**)&rowptr, g_rowptr);
    cudaGetSymbolAddress((void**)&wofs,   g_wofs);
    cudaGetSymbolAddress((void**)&col,    g_col);

    const int* srcp = ei;
    const int* dstp = ei + e;

    // graph preprocessing (once per call, reused by all 4 propagation passes)
    k_zero_counts<<<(n + 255) / 256, 256>>>(counts, n);
    k_count<<<(e + 255) / 256, 256>>>(dstp, counts, e);
    k_scan<<<1, 1024>>>(counts, rowptr, n);
    k_aux<<<(n + 255) / 256, 256>>>(rowptr, counts, wofs, dinv, n);
    k_fill<<<(e + 255) / 256, 256>>>(srcp, dstp, wofs, col, e);
    k_pack<<<(D * D + 255) / 256, 256>>>(Wmu, Wlv, bmu, blv, Wcat, bcat);

    const int gemm_grid = (n + 63) / 64;
    const int prop_grid = (n + 7) / 8;      // 8 warps (nodes) / block
    const int elem_grid = (n * 32 + 255) / 256;

    const float* xcur = x;
    float* bufs[2] = {x1, x2};
    for (int l = 0; l < 3; l++) {
        k_gemm<<<gemm_grid, 256>>>(xcur, Ws + l * D * D, h, n);
        k_prop<false><<<prop_grid, 256>>>((const float4*)h, dinv, rowptr, col,
                                          bs + l * D, (float4*)agg, nullptr, n);
        k_zero_stats<<<1, 256>>>(stats);
        k_bnstats<<<(n + 63) / 64, 256>>>(agg, stats, n);
        float* xnext = bufs[l & 1];
        k_bnapply<<<elem_grid, 256>>>((const float4*)agg, stats, gamma, beta,
                                      (const float4*)xcur, (float4*)xnext, n);
        xcur = xnext;
    }

    // heads: one GEMM with [Wmu | Wlv], one propagation writing both outputs
    k_gemm<<<gemm_grid, 256>>>(xcur, Wcat, h, n);
    k_prop<true><<<prop_grid, 256>>>((const float4*)h, dinv, rowptr, col,
                                     bcat, (float4*)out,
                                     (float4*)(out + (size_t)n * LDIM), n);
}

// round 4
// speedup vs baseline: 1.2258x; 1.2258x over previous
#include <cuda_runtime.h>
#include <cstdint>

#define D     128
#define LDIM  64
#define NMAX  50000
#define EMAX  625000
#define EPS   1e-5f
#define SLOPE 0.01f

// ---------------- scratch (static device globals; no allocation) ----------------
__device__ float g_h   [NMAX * D];
__device__ float g_aggA[NMAX * D];
__device__ float g_aggB[NMAX * D];
__device__ float g_x1  [NMAX * D];
__device__ float g_x2  [NMAX * D];
__device__ float g_dinv[NMAX];
__device__ int   g_counts[NMAX];
__device__ int   g_rowptr[NMAX + 1];
__device__ int   g_wofs[NMAX];
__device__ int   g_col[EMAX];
__device__ float g_stats[3 * 2 * D];   // per-layer [sum(128), sumsq(128)]
__device__ float g_Wcat[D * D];
__device__ float g_bcat[D];

// ---------------- graph preprocessing ----------------
__global__ void k_zero_counts(int* counts, int n) {
    int i = blockIdx.x * blockDim.x + threadIdx.x;
    if (i < n) counts[i] = 0;
}

__global__ void k_count(const int* __restrict__ dst, int* counts, int e) {
    int i = blockIdx.x * blockDim.x + threadIdx.x;
    if (i < e) atomicAdd(&counts[dst[i]], 1);
}

// single-block warp-shuffle scan -> exclusive rowptr
__global__ void k_scan(const int* __restrict__ counts, int* rowptr, int n) {
    __shared__ int ws[32];
    __shared__ int carry;
    const int tid = threadIdx.x;
    const int lane = tid & 31, wid = tid >> 5;
    if (tid == 0) { carry = 0; rowptr[0] = 0; }
    __syncthreads();
    for (int base = 0; base < n; base += 1024) {
        int i = base + tid;
        int v = (i < n) ? counts[i] : 0;
        int s = v;
        #pragma unroll
        for (int off = 1; off < 32; off <<= 1) {
            int t = __shfl_up_sync(0xffffffffu, s, off);
            if (lane >= off) s += t;
        }
        if (lane == 31) ws[wid] = s;
        __syncthreads();
        if (wid == 0) {
            int t2 = ws[lane];
            #pragma unroll
            for (int off = 1; off < 32; off <<= 1) {
                int t = __shfl_up_sync(0xffffffffu, t2, off);
                if (lane >= off) t2 += t;
            }
            ws[lane] = t2;
        }
        __syncthreads();
        int add = carry + (wid ? ws[wid - 1] : 0);
        if (i < n) rowptr[i + 1] = add + s;
        __syncthreads();
        if (tid == 0) carry += ws[31];
        __syncthreads();
    }
}

__global__ void k_aux_pack(const int* __restrict__ rowptr, const int* __restrict__ counts,
                           int* wofs, float* dinv,
                           const float* __restrict__ Wmu, const float* __restrict__ Wlv,
                           const float* __restrict__ bmu, const float* __restrict__ blv,
                           float* Wcat, float* bcat, float* stats, int n) {
    int i = blockIdx.x * blockDim.x + threadIdx.x;
    if (i < n) {
        wofs[i] = rowptr[i];
        dinv[i] = rsqrtf((float)(counts[i] + 1));   // +1 self-loop
    }
    if (i < D * D) {
        int k = i >> 7, c = i & 127;
        Wcat[i] = (c < LDIM) ? Wmu[k * LDIM + c] : Wlv[k * LDIM + (c - LDIM)];
    }
    if (i < D) bcat[i] = (i < LDIM) ? bmu[i] : blv[i - LDIM];
    if (i < 3 * 2 * D) stats[i] = 0.f;
}

__global__ void k_fill(const int* __restrict__ src, const int* __restrict__ dst,
                       int* wofs, int* col, int e) {
    int i = blockIdx.x * blockDim.x + threadIdx.x;
    if (i < e) {
        int d = dst[i];
        int pos = atomicAdd(&wofs[d], 1);
        col[pos] = src[i];
    }
}

// ---------------- tf32 tensor-core GEMM with 3-term split ----------------
__device__ __forceinline__ uint32_t f2tf(float x) {
    uint32_t r;
    asm("cvt.rna.tf32.f32 %0, %1;" : "=r"(r) : "f"(x));
    return r;
}

__device__ __forceinline__ void mma8(float* d, const uint32_t* a, const uint32_t* b) {
    asm volatile(
        "mma.sync.aligned.m16n8k8.row.col.f32.tf32.tf32.f32 "
        "{%0,%1,%2,%3}, {%4,%5,%6,%7}, {%8,%9}, {%0,%1,%2,%3};"
        : "+f"(d[0]), "+f"(d[1]), "+f"(d[2]), "+f"(d[3])
        : "r"(a[0]), "r"(a[1]), "r"(a[2]), "r"(a[3]), "r"(b[0]), "r"(b[1]));
}

// C[M,128] = A'[M,128] @ B[128,128], where A' = lrelu(BN(A))+xres when FUSE.
// Block: 64 rows x 128 cols, 8 warps (4 along M x 2 along N), whole K resident.
// Smem (dynamic, 99328 B): A frags 8192 f, B frags 16384 f, SC/SF 256 f.
template <bool FUSE, bool WRITE_X>
__global__ __launch_bounds__(256) void k_gemm(const float* __restrict__ A,
                                              const float* __restrict__ B,
                                              float* __restrict__ C,
                                              const float* __restrict__ stats,
                                              const float* __restrict__ gamma,
                                              const float* __restrict__ beta,
                                              const float* __restrict__ xres,
                                              float* __restrict__ xout, int M) {
    extern __shared__ float sm[];
    float* As = sm;             // 8192: [kt(16)][mt(4)][lane(32)][j(4)]
    float* Bs = sm + 8192;      // 16384: [kt(16)][nt(16)][lane(32)][j(2)]
    float* SC = sm + 24576;     // 128
    float* SF = sm + 24704;     // 128

    const int tid  = threadIdx.x;
    const int lane = tid & 31;
    const int warp = tid >> 5;
    const int wm = warp >> 1;   // 0..3
    const int wn = warp & 1;    // 0..1
    const int row0 = blockIdx.x * 64;

    if (FUSE) {
        if (tid < 128) {
            float inv_n = 1.f / (float)M;
            float mean = stats[tid] * inv_n;
            float var  = stats[128 + tid] * inv_n - mean * mean;
            float s = gamma[tid] * rsqrtf(var + EPS);
            SC[tid] = s;
            SF[tid] = beta[tid] - mean * s;
        }
        __syncthreads();
    }

    // B -> fragment-major smem (coalesced global read)
    #pragma unroll
    for (int i = tid; i < 16384; i += 256) {
        int k = i >> 7, nn = i & 127;
        int kt = k >> 3, ki = k & 7, nt = nn >> 3, ni = nn & 7;
        Bs[((kt * 16 + nt) * 32 + ni * 4 + (ki & 3)) * 2 + (ki >> 2)] = B[i];
    }
    // A -> fragment-major smem, with fused BN/lrelu/residual
    #pragma unroll
    for (int i = tid; i < 8192; i += 256) {
        int m = i >> 7, k = i & 127;
        int gr = row0 + m;
        float v = 0.f;
        if (gr < M) {
            v = A[gr * 128 + k];
            if (FUSE) {
                v = fmaf(v, SC[k], SF[k]);
                v = (v >= 0.f) ? v : SLOPE * v;
                v += xres[gr * 128 + k];
                if (WRITE_X) xout[gr * 128 + k] = v;
            }
        }
        int mt = m >> 4, mi = m & 15, kt = k >> 3, ki = k & 7;
        As[((kt * 4 + mt) * 32 + (mi & 7) * 4 + (ki & 3)) * 4 +
           ((ki >> 2) * 2 + (mi >> 3))] = v;
    }
    __syncthreads();

    float acc[8][4];
    #pragma unroll
    for (int nt = 0; nt < 8; nt++)
        #pragma unroll
        for (int j = 0; j < 4; j++) acc[nt][j] = 0.f;

    #pragma unroll 4
    for (int kt = 0; kt < 16; kt++) {
        float4 av = *(const float4*)&As[((kt * 4 + wm) * 32 + lane) * 4];
        float af[4] = {av.x, av.y, av.z, av.w};
        uint32_t ah[4], al[4];
        #pragma unroll
        for (int j = 0; j < 4; j++) {
            ah[j] = f2tf(af[j]);
            al[j] = f2tf(af[j] - __uint_as_float(ah[j]));
        }
        #pragma unroll
        for (int nt = 0; nt < 8; nt++) {
            float2 bv = *(const float2*)&Bs[((kt * 16 + wn * 8 + nt) * 32 + lane) * 2];
            uint32_t bh[2], bl[2];
            bh[0] = f2tf(bv.x); bl[0] = f2tf(bv.x - __uint_as_float(bh[0]));
            bh[1] = f2tf(bv.y); bl[1] = f2tf(bv.y - __uint_as_float(bh[1]));
            mma8(acc[nt], ah, bh);
            mma8(acc[nt], ah, bl);
            mma8(acc[nt], al, bh);
        }
    }

    // epilogue: c0,c1 = (g, 2t),(g,2t+1); c2,c3 = (g+8, 2t),(g+8,2t+1)
    const int g = lane >> 2, t = lane & 3;
    const int r0 = row0 + wm * 16 + g;
    #pragma unroll
    for (int nt = 0; nt < 8; nt++) {
        int c0 = wn * 64 + nt * 8 + t * 2;
        if (r0 < M)
            *(float2*)&C[r0 * 128 + c0] = make_float2(acc[nt][0], acc[nt][1]);
        if (r0 + 8 < M)
            *(float2*)&C[(r0 + 8) * 128 + c0] = make_float2(acc[nt][2], acc[nt][3]);
    }
}

// ---------------- propagation (+ fused BN statistics) ----------------
// out[d] = dinv[d]*(sum_s dinv[s] h[s] + dinv[d] h[d]) + b ; 32 nodes/block.
template <bool SPLIT, bool STATS>
__global__ __launch_bounds__(256) void k_prop(const float4* __restrict__ h4,
                                              const float* __restrict__ dinv,
                                              const int* __restrict__ rowptr,
                                              const int* __restrict__ col,
                                              const float* __restrict__ bias,
                                              float4* __restrict__ out_a,
                                              float4* __restrict__ out_b,
                                              float* __restrict__ stats, int n) {
    __shared__ float s_red[256];
    const int lane = threadIdx.x & 31;
    const int warp = threadIdx.x >> 5;
    if (STATS) {
        s_red[threadIdx.x] = 0.f;
        __syncthreads();
    }
    const float4 b4 = *(const float4*)(bias + lane * 4);
    float4 ps = make_float4(0.f, 0.f, 0.f, 0.f);
    float4 pq = make_float4(0.f, 0.f, 0.f, 0.f);
    const int base = blockIdx.x * 32 + warp * 4;
    for (int i = 0; i < 4; i++) {
        int w = base + i;
        if (w >= n) break;
        float dd = dinv[w];
        float4 v = h4[w * 32 + lane];
        float4 acc;
        acc.x = dd * v.x; acc.y = dd * v.y; acc.z = dd * v.z; acc.w = dd * v.w;
        int beg = rowptr[w], end = rowptr[w + 1];
        for (int e = beg; e < end; e++) {
            int s = col[e];
            float ds = dinv[s];
            float4 u = h4[s * 32 + lane];
            acc.x = fmaf(ds, u.x, acc.x);
            acc.y = fmaf(ds, u.y, acc.y);
            acc.z = fmaf(ds, u.z, acc.z);
            acc.w = fmaf(ds, u.w, acc.w);
        }
        acc.x = fmaf(acc.x, dd, b4.x);
        acc.y = fmaf(acc.y, dd, b4.y);
        acc.z = fmaf(acc.z, dd, b4.z);
        acc.w = fmaf(acc.w, dd, b4.w);
        if (STATS) {
            ps.x += acc.x; ps.y += acc.y; ps.z += acc.z; ps.w += acc.w;
            pq.x += acc.x * acc.x; pq.y += acc.y * acc.y;
            pq.z += acc.z * acc.z; pq.w += acc.w * acc.w;
        }
        if (!SPLIT) {
            out_a[w * 32 + lane] = acc;
        } else {
            if (lane < 16) out_a[w * 16 + lane]        = acc;   // mu
            else           out_b[w * 16 + (lane - 16)] = acc;   // logvar
        }
    }
    if (STATS) {
        atomicAdd(&s_red[lane * 4 + 0], ps.x);
        atomicAdd(&s_red[lane * 4 + 1], ps.y);
        atomicAdd(&s_red[lane * 4 + 2], ps.z);
        atomicAdd(&s_red[lane * 4 + 3], ps.w);
        atomicAdd(&s_red[128 + lane * 4 + 0], pq.x);
        atomicAdd(&s_red[128 + lane * 4 + 1], pq.y);
        atomicAdd(&s_red[128 + lane * 4 + 2], pq.z);
        atomicAdd(&s_red[128 + lane * 4 + 3], pq.w);
        __syncthreads();
        atomicAdd(&stats[threadIdx.x], s_red[threadIdx.x]);
    }
}

// ---------------- launcher ----------------
extern "C" void kernel_launch(void* const* d_in, const int* in_sizes, int n_in,
                              void* d_out, int out_size) {
    const float* x     = (const float*)d_in[0];
    const int*   ei    = (const int*)d_in[1];     // int32 (jax x64 disabled)
    const float* Ws    = (const float*)d_in[2];
    const float* bs    = (const float*)d_in[3];
    const float* Wmu   = (const float*)d_in[4];
    const float* bmu   = (const float*)d_in[5];
    const float* Wlv   = (const float*)d_in[6];
    const float* blv   = (const float*)d_in[7];
    const float* gamma = (const float*)d_in[8];
    const float* beta  = (const float*)d_in[9];

    const int n = in_sizes[0] / D;
    const int e = in_sizes[1] / 2;
    float* out = (float*)d_out;

    float *h, *aggA, *aggB, *x1, *x2, *dinv, *stats, *Wcat, *bcat;
    int *counts, *rowptr, *wofs, *col;
    cudaGetSymbolAddress((void**)&h,      g_h);
    cudaGetSymbolAddress((void**)&aggA,   g_aggA);
    cudaGetSymbolAddress((void**)&aggB,   g_aggB);
    cudaGetSymbolAddress((void**)&x1,     g_x1);
    cudaGetSymbolAddress((void**)&x2,     g_x2);
    cudaGetSymbolAddress((void**)&dinv,   g_dinv);
    cudaGetSymbolAddress((void**)&stats,  g_stats);
    cudaGetSymbolAddress((void**)&Wcat,   g_Wcat);
    cudaGetSymbolAddress((void**)&bcat,   g_bcat);
    cudaGetSymbolAddress((void**)&counts, g_counts);
    cudaGetSymbolAddress((void**)&rowptr, g_rowptr);
    cudaGetSymbolAddress((void**)&wofs,   g_wofs);
    cudaGetSymbolAddress((void**)&col,    g_col);

    const int* srcp = ei;
    const int* dstp = ei + e;

    const int SMEM = 24832 * (int)sizeof(float);   // 99328 B
    cudaFuncSetAttribute(k_gemm<false, false>,
                         cudaFuncAttributeMaxDynamicSharedMemorySize, SMEM);
    cudaFuncSetAttribute(k_gemm<true, true>,
                         cudaFuncAttributeMaxDynamicSharedMemorySize, SMEM);
    cudaFuncSetAttribute(k_gemm<true, false>,
                         cudaFuncAttributeMaxDynamicSharedMemorySize, SMEM);

    // preprocessing (CSR + dinv + packed head weights + zeroed stats)
    k_zero_counts<<<(n + 255) / 256, 256>>>(counts, n);
    k_count<<<(e + 255) / 256, 256>>>(dstp, counts, e);
    k_scan<<<1, 1024>>>(counts, rowptr, n);
    k_aux_pack<<<(n + 255) / 256, 256>>>(rowptr, counts, wofs, dinv,
                                         Wmu, Wlv, bmu, blv, Wcat, bcat, stats, n);
    k_fill<<<(e + 255) / 256, 256>>>(srcp, dstp, wofs, col, e);

    const int gemm_grid = (n + 63) / 64;
    const int prop_grid = (n + 31) / 32;

    // layer 0
    k_gemm<false, false><<<gemm_grid, 256, SMEM>>>(x, Ws, h, nullptr, nullptr,
                                                   nullptr, nullptr, nullptr, n);
    k_prop<false, true><<<prop_grid, 256>>>((const float4*)h, dinv, rowptr, col,
                                            bs, (float4*)aggA, nullptr, stats, n);
    // layer 1 (GEMM applies BN of layer 0)
    k_gemm<true, true><<<gemm_grid, 256, SMEM>>>(aggA, Ws + D * D, h, stats,
                                                 gamma, beta, x, x1, n);
    k_prop<false, true><<<prop_grid, 256>>>((const float4*)h, dinv, rowptr, col,
                                            bs + D, (float4*)aggB, nullptr,
                                            stats + 256, n);
    // layer 2 (GEMM applies BN of layer 1)
    k_gemm<true, true><<<gemm_grid, 256, SMEM>>>(aggB, Ws + 2 * D * D, h,
                                                 stats + 256, gamma, beta, x1, x2, n);
    k_prop<false, true><<<prop_grid, 256>>>((const float4*)h, dinv, rowptr, col,
                                            bs + 2 * D, (float4*)aggA, nullptr,
                                            stats + 512, n);
    // heads (GEMM applies BN of layer 2; no x-write needed)
    k_gemm<true, false><<<gemm_grid, 256, SMEM>>>(aggA, Wcat, h, stats + 512,
                                                  gamma, beta, x2, nullptr, n);
    k_prop<true, false><<<prop_grid, 256>>>((const float4*)h, dinv, rowptr, col,
                                            bcat, (float4*)out,
                                            (float4*)(out + (size_t)n * LDIM),
                                            nullptr, n);
}

// round 5
// speedup vs baseline: 1.3647x; 1.1133x over previous
#include <cuda_runtime.h>
#include <cstdint>

#define D     128
#define LDIM  64
#define NMAX  50000
#define EMAX  625000
#define EPS   1e-5f
#define SLOPE 0.01f

// ---------------- scratch (static device globals; no allocation) ----------------
__device__ float g_h   [NMAX * D];
__device__ float g_aggA[NMAX * D];
__device__ float g_aggB[NMAX * D];
__device__ float g_x1  [NMAX * D];
__device__ float g_x2  [NMAX * D];
__device__ float g_dinv[NMAX];
__device__ int   g_counts[NMAX];
__device__ int   g_rowptr[NMAX + 1];
__device__ int   g_linc[NMAX];        // per-block inclusive scans (temp)
__device__ int   g_bsums[128];        // block sums for scan
__device__ int   g_wofs[NMAX];
__device__ int   g_col[EMAX];
__device__ float g_stats[3 * 2 * D];  // per-layer [sum(128), sumsq(128)]
__device__ float g_Wcat[D * D];
__device__ float g_bcat[D];

// ---------------- graph preprocessing ----------------
__global__ void k_count(const int* __restrict__ dst, int* counts, int e) {
    int i = blockIdx.x * blockDim.x + threadIdx.x;
    if (i < e) atomicAdd(&counts[dst[i]], 1);
}

// per-block (1024) inclusive scan; write local inclusive to linc, block total to bsums
__global__ __launch_bounds__(1024) void k_scan1(const int* __restrict__ counts,
                                                int* linc, int* bsums, int n) {
    __shared__ int ws[32];
    const int tid = threadIdx.x, lane = tid & 31, wid = tid >> 5;
    int i = blockIdx.x * 1024 + tid;
    int v = (i < n) ? counts[i] : 0;
    int s = v;
    #pragma unroll
    for (int off = 1; off < 32; off <<= 1) {
        int t = __shfl_up_sync(0xffffffffu, s, off);
        if (lane >= off) s += t;
    }
    if (lane == 31) ws[wid] = s;
    __syncthreads();
    if (wid == 0) {
        int t2 = ws[lane];
        #pragma unroll
        for (int off = 1; off < 32; off <<= 1) {
            int t = __shfl_up_sync(0xffffffffu, t2, off);
            if (lane >= off) t2 += t;
        }
        ws[lane] = t2;
    }
    __syncthreads();
    int inc = s + (wid ? ws[wid - 1] : 0);
    if (i < n) linc[i] = inc;
    if (tid == 1023) bsums[blockIdx.x] = inc;
}

// single-block exclusive scan of block sums (<=128 entries)
__global__ void k_scan2(int* bsums, int nb) {
    __shared__ int sh[128];
    int tid = threadIdx.x;
    sh[tid] = (tid < nb) ? bsums[tid] : 0;
    __syncthreads();
    #pragma unroll
    for (int off = 1; off < 128; off <<= 1) {
        int t = (tid >= off) ? sh[tid - off] : 0;
        __syncthreads();
        sh[tid] += t;
        __syncthreads();
    }
    if (tid < nb) bsums[tid] = (tid == 0) ? 0 : sh[tid - 1];   // exclusive
}

// finalize rowptr + wofs + dinv + pack head weights
__global__ void k_aux_pack(const int* __restrict__ linc, const int* __restrict__ bsums,
                           const int* __restrict__ counts,
                           int* rowptr, int* wofs, float* dinv,
                           const float* __restrict__ Wmu, const float* __restrict__ Wlv,
                           const float* __restrict__ bmu, const float* __restrict__ blv,
                           float* Wcat, float* bcat, int n) {
    int i = blockIdx.x * blockDim.x + threadIdx.x;
    if (i < n) {
        int rp1 = linc[i] + bsums[i >> 10];
        rowptr[i + 1] = rp1;
        wofs[i] = rp1 - counts[i];            // == final rowptr[i]
        dinv[i] = rsqrtf((float)(counts[i] + 1));   // +1 self-loop
        if (i == 0) rowptr[0] = 0;
    }
    if (i < D * D) {
        int k = i >> 7, c = i & 127;
        Wcat[i] = (c < LDIM) ? Wmu[k * LDIM + c] : Wlv[k * LDIM + (c - LDIM)];
    }
    if (i < D) bcat[i] = (i < LDIM) ? bmu[i] : blv[i - LDIM];
}

__global__ void k_fill(const int* __restrict__ src, const int* __restrict__ dst,
                       int* wofs, int* col, int e) {
    int i = blockIdx.x * blockDim.x + threadIdx.x;
    if (i < e) {
        int d = dst[i];
        int pos = atomicAdd(&wofs[d], 1);
        col[pos] = src[i];
    }
}

// ---------------- tf32 tensor-core GEMM with 3-term split ----------------
__device__ __forceinline__ uint32_t f2tf(float x) {
    uint32_t r;
    asm("cvt.rna.tf32.f32 %0, %1;" : "=r"(r) : "f"(x));
    return r;
}

__device__ __forceinline__ void mma8(float* d, const uint32_t* a, const uint32_t* b) {
    asm volatile(
        "mma.sync.aligned.m16n8k8.row.col.f32.tf32.tf32.f32 "
        "{%0,%1,%2,%3}, {%4,%5,%6,%7}, {%8,%9}, {%0,%1,%2,%3};"
        : "+f"(d[0]), "+f"(d[1]), "+f"(d[2]), "+f"(d[3])
        : "r"(a[0]), "r"(a[1]), "r"(a[2]), "r"(a[3]), "r"(b[0]), "r"(b[1]));
}

// C[M,128] = dinv[m] * (A'[M,128] @ B[128,128]), A' = lrelu(BN(A))+xres when FUSE.
// Block: 64 rows x 128 cols, 8 warps (4 along M x 2 along N), whole K resident.
template <bool FUSE, bool WRITE_X>
__global__ __launch_bounds__(256) void k_gemm(const float* __restrict__ A,
                                              const float* __restrict__ B,
                                              float* __restrict__ C,
                                              const float* __restrict__ dinv,
                                              const float* __restrict__ stats,
                                              const float* __restrict__ gamma,
                                              const float* __restrict__ beta,
                                              const float* __restrict__ xres,
                                              float* __restrict__ xout, int M) {
    extern __shared__ float sm[];
    float* As = sm;             // 8192: [kt(16)][mt(4)][lane(32)][j(4)]
    float* Bs = sm + 8192;      // 16384: [kt(16)][nt(16)][lane(32)][j(2)]
    float* SC = sm + 24576;     // 128
    float* SF = sm + 24704;     // 128

    const int tid  = threadIdx.x;
    const int lane = tid & 31;
    const int warp = tid >> 5;
    const int wm = warp >> 1;   // 0..3
    const int wn = warp & 1;    // 0..1
    const int row0 = blockIdx.x * 64;

    if (FUSE) {
        if (tid < 128) {
            float inv_n = 1.f / (float)M;
            float mean = stats[tid] * inv_n;
            float var  = stats[128 + tid] * inv_n - mean * mean;
            float s = gamma[tid] * rsqrtf(var + EPS);
            SC[tid] = s;
            SF[tid] = beta[tid] - mean * s;
        }
        __syncthreads();
    }

    #pragma unroll
    for (int i = tid; i < 16384; i += 256) {
        int k = i >> 7, nn = i & 127;
        int kt = k >> 3, ki = k & 7, nt = nn >> 3, ni = nn & 7;
        Bs[((kt * 16 + nt) * 32 + ni * 4 + (ki & 3)) * 2 + (ki >> 2)] = B[i];
    }
    #pragma unroll
    for (int i = tid; i < 8192; i += 256) {
        int m = i >> 7, k = i & 127;
        int gr = row0 + m;
        float v = 0.f;
        if (gr < M) {
            v = A[gr * 128 + k];
            if (FUSE) {
                v = fmaf(v, SC[k], SF[k]);
                v = (v >= 0.f) ? v : SLOPE * v;
                v += xres[gr * 128 + k];
                if (WRITE_X) xout[gr * 128 + k] = v;
            }
        }
        int mt = m >> 4, mi = m & 15, kt = k >> 3, ki = k & 7;
        As[((kt * 4 + mt) * 32 + (mi & 7) * 4 + (ki & 3)) * 4 +
           ((ki >> 2) * 2 + (mi >> 3))] = v;
    }
    __syncthreads();

    float acc[8][4];
    #pragma unroll
    for (int nt = 0; nt < 8; nt++)
        #pragma unroll
        for (int j = 0; j < 4; j++) acc[nt][j] = 0.f;

    #pragma unroll 4
    for (int kt = 0; kt < 16; kt++) {
        float4 av = *(const float4*)&As[((kt * 4 + wm) * 32 + lane) * 4];
        float af[4] = {av.x, av.y, av.z, av.w};
        uint32_t ah[4], al[4];
        #pragma unroll
        for (int j = 0; j < 4; j++) {
            ah[j] = f2tf(af[j]);
            al[j] = f2tf(af[j] - __uint_as_float(ah[j]));
        }
        #pragma unroll
        for (int nt = 0; nt < 8; nt++) {
            float2 bv = *(const float2*)&Bs[((kt * 16 + wn * 8 + nt) * 32 + lane) * 2];
            uint32_t bh[2], bl[2];
            bh[0] = f2tf(bv.x); bl[0] = f2tf(bv.x - __uint_as_float(bh[0]));
            bh[1] = f2tf(bv.y); bl[1] = f2tf(bv.y - __uint_as_float(bh[1]));
            mma8(acc[nt], ah, bh);
            mma8(acc[nt], ah, bl);
            mma8(acc[nt], al, bh);
        }
    }

    // epilogue: rows (r0, r0+8), pre-scaled by dinv
    const int g = lane >> 2, t = lane & 3;
    const int r0 = row0 + wm * 16 + g;
    const float s0 = (r0 < M)     ? dinv[r0]     : 0.f;
    const float s1 = (r0 + 8 < M) ? dinv[r0 + 8] : 0.f;
    #pragma unroll
    for (int nt = 0; nt < 8; nt++) {
        int c0 = wn * 64 + nt * 8 + t * 2;
        if (r0 < M)
            *(float2*)&C[r0 * 128 + c0] = make_float2(acc[nt][0] * s0, acc[nt][1] * s0);
        if (r0 + 8 < M)
            *(float2*)&C[(r0 + 8) * 128 + c0] = make_float2(acc[nt][2] * s1, acc[nt][3] * s1);
    }
}

// ---------------- propagation (+ fused BN statistics) ----------------
// h' is pre-scaled by dinv. out[d] = dinv[d]*(sum_s h'[s] + h'[d]) + b.
template <bool SPLIT, bool STATS>
__global__ __launch_bounds__(256) void k_prop(const float4* __restrict__ h4,
                                              const float* __restrict__ dinv,
                                              const int* __restrict__ rowptr,
                                              const int* __restrict__ col,
                                              const float* __restrict__ bias,
                                              float4* __restrict__ out_a,
                                              float4* __restrict__ out_b,
                                              float* __restrict__ stats, int n) {
    __shared__ float s_red[256];
    const int lane = threadIdx.x & 31;
    const int warp = threadIdx.x >> 5;
    if (STATS) {
        s_red[threadIdx.x] = 0.f;
        __syncthreads();
    }
    const float4 b4 = *(const float4*)(bias + lane * 4);
    float4 ps = make_float4(0.f, 0.f, 0.f, 0.f);
    float4 pq = make_float4(0.f, 0.f, 0.f, 0.f);
    const int base = blockIdx.x * 32 + warp * 4;
    for (int i = 0; i < 4; i++) {
        int w = base + i;
        if (w >= n) break;
        float dd = dinv[w];
        float4 a0 = h4[w * 32 + lane];                  // self term (pre-scaled)
        float4 a1 = make_float4(0.f, 0.f, 0.f, 0.f);
        int e = rowptr[w];
        const int end = rowptr[w + 1];
        for (; e + 2 <= end; e += 2) {
            int s0 = col[e], s1 = col[e + 1];
            float4 u0 = h4[s0 * 32 + lane];
            float4 u1 = h4[s1 * 32 + lane];
            a0.x += u0.x; a0.y += u0.y; a0.z += u0.z; a0.w += u0.w;
            a1.x += u1.x; a1.y += u1.y; a1.z += u1.z; a1.w += u1.w;
        }
        if (e < end) {
            float4 u0 = h4[col[e] * 32 + lane];
            a0.x += u0.x; a0.y += u0.y; a0.z += u0.z; a0.w += u0.w;
        }
        float4 acc;
        acc.x = fmaf(a0.x + a1.x, dd, b4.x);
        acc.y = fmaf(a0.y + a1.y, dd, b4.y);
        acc.z = fmaf(a0.z + a1.z, dd, b4.z);
        acc.w = fmaf(a0.w + a1.w, dd, b4.w);
        if (STATS) {
            ps.x += acc.x; ps.y += acc.y; ps.z += acc.z; ps.w += acc.w;
            pq.x += acc.x * acc.x; pq.y += acc.y * acc.y;
            pq.z += acc.z * acc.z; pq.w += acc.w * acc.w;
        }
        if (!SPLIT) {
            out_a[w * 32 + lane] = acc;
        } else {
            if (lane < 16) out_a[w * 16 + lane]        = acc;   // mu
            else           out_b[w * 16 + (lane - 16)] = acc;   // logvar
        }
    }
    if (STATS) {
        atomicAdd(&s_red[lane * 4 + 0], ps.x);
        atomicAdd(&s_red[lane * 4 + 1], ps.y);
        atomicAdd(&s_red[lane * 4 + 2], ps.z);
        atomicAdd(&s_red[lane * 4 + 3], ps.w);
        atomicAdd(&s_red[128 + lane * 4 + 0], pq.x);
        atomicAdd(&s_red[128 + lane * 4 + 1], pq.y);
        atomicAdd(&s_red[128 + lane * 4 + 2], pq.z);
        atomicAdd(&s_red[128 + lane * 4 + 3], pq.w);
        __syncthreads();
        atomicAdd(&stats[threadIdx.x], s_red[threadIdx.x]);
    }
}

// ---------------- launcher ----------------
extern "C" void kernel_launch(void* const* d_in, const int* in_sizes, int n_in,
                              void* d_out, int out_size) {
    const float* x     = (const float*)d_in[0];
    const int*   ei    = (const int*)d_in[1];     // int32 (jax x64 disabled)
    const float* Ws    = (const float*)d_in[2];
    const float* bs    = (const float*)d_in[3];
    const float* Wmu   = (const float*)d_in[4];
    const float* bmu   = (const float*)d_in[5];
    const float* Wlv   = (const float*)d_in[6];
    const float* blv   = (const float*)d_in[7];
    const float* gamma = (const float*)d_in[8];
    const float* beta  = (const float*)d_in[9];

    const int n = in_sizes[0] / D;
    const int e = in_sizes[1] / 2;
    float* out = (float*)d_out;

    float *h, *aggA, *aggB, *x1, *x2, *dinv, *stats, *Wcat, *bcat;
    int *counts, *rowptr, *linc, *bsums, *wofs, *col;
    cudaGetSymbolAddress((void**)&h,      g_h);
    cudaGetSymbolAddress((void**)&aggA,   g_aggA);
    cudaGetSymbolAddress((void**)&aggB,   g_aggB);
    cudaGetSymbolAddress((void**)&x1,     g_x1);
    cudaGetSymbolAddress((void**)&x2,     g_x2);
    cudaGetSymbolAddress((void**)&dinv,   g_dinv);
    cudaGetSymbolAddress((void**)&stats,  g_stats);
    cudaGetSymbolAddress((void**)&Wcat,   g_Wcat);
    cudaGetSymbolAddress((void**)&bcat,   g_bcat);
    cudaGetSymbolAddress((void**)&counts, g_counts);
    cudaGetSymbolAddress((void**)&rowptr, g_rowptr);
    cudaGetSymbolAddress((void**)&linc,   g_linc);
    cudaGetSymbolAddress((void**)&bsums,  g_bsums);
    cudaGetSymbolAddress((void**)&wofs,   g_wofs);
    cudaGetSymbolAddress((void**)&col,    g_col);

    const int* srcp = ei;
    const int* dstp = ei + e;

    const int SMEM = 24832 * (int)sizeof(float);   // 99328 B
    cudaFuncSetAttribute(k_gemm<false, false>,
                         cudaFuncAttributeMaxDynamicSharedMemorySize, SMEM);
    cudaFuncSetAttribute(k_gemm<true, true>,
                         cudaFuncAttributeMaxDynamicSharedMemorySize, SMEM);
    cudaFuncSetAttribute(k_gemm<true, false>,
                         cudaFuncAttributeMaxDynamicSharedMemorySize, SMEM);

    // preprocessing (CSR + dinv + packed head weights + zeroed stats)
    cudaMemsetAsync(counts, 0, (size_t)n * sizeof(int));
    cudaMemsetAsync(stats, 0, 3 * 2 * D * sizeof(float));
    const int nb = (n + 1023) / 1024;
    k_count<<<(e + 255) / 256, 256>>>(dstp, counts, e);
    k_scan1<<<nb, 1024>>>(counts, linc, bsums, n);
    k_scan2<<<1, 128>>>(bsums, nb);
    k_aux_pack<<<(n + 255) / 256, 256>>>(linc, bsums, counts, rowptr, wofs, dinv,
                                         Wmu, Wlv, bmu, blv, Wcat, bcat, n);
    k_fill<<<(e + 255) / 256, 256>>>(srcp, dstp, wofs, col, e);

    const int gemm_grid = (n + 63) / 64;
    const int prop_grid = (n + 31) / 32;

    // layer 0
    k_gemm<false, false><<<gemm_grid, 256, SMEM>>>(x, Ws, h, dinv, nullptr,
                                                   nullptr, nullptr, nullptr,
                                                   nullptr, n);
    k_prop<false, true><<<prop_grid, 256>>>((const float4*)h, dinv, rowptr, col,
                                            bs, (float4*)aggA, nullptr, stats, n);
    // layer 1 (GEMM applies BN of layer 0)
    k_gemm<true, true><<<gemm_grid, 256, SMEM>>>(aggA, Ws + D * D, h, dinv, stats,
                                                 gamma, beta, x, x1, n);
    k_prop<false, true><<<prop_grid, 256>>>((const float4*)h, dinv, rowptr, col,
                                            bs + D, (float4*)aggB, nullptr,
                                            stats + 256, n);
    // layer 2 (GEMM applies BN of layer 1)
    k_gemm<true, true><<<gemm_grid, 256, SMEM>>>(aggB, Ws + 2 * D * D, h, dinv,
                                                 stats + 256, gamma, beta, x1, x2, n);
    k_prop<false, true><<<prop_grid, 256>>>((const float4*)h, dinv, rowptr, col,
                                            bs + 2 * D, (float4*)aggA, nullptr,
                                            stats + 512, n);
    // heads (GEMM applies BN of layer 2; no x-write needed)
    k_gemm<true, false><<<gemm_grid, 256, SMEM>>>(aggA, Wcat, h, dinv, stats + 512,
                                                  gamma, beta, x2, nullptr, n);
    k_prop<true, false><<<prop_grid, 256>>>((const float4*)h, dinv, rowptr, col,
                                            bcat, (float4*)out,
                                            (float4*)(out + (size_t)n * LDIM),
                                            nullptr, n);
}

// round 7
// speedup vs baseline: 1.4378x; 1.0536x over previous
#include <cuda_runtime.h>
#include <cuda_fp16.h>
#include <cstdint>

#define D     128
#define LDIM  64
#define NMAX  50000
#define EMAX  625000
#define EPS   1e-5f
#define SLOPE 0.01f

// ---------------- scratch (static device globals; no allocation) ----------------
__device__ __half g_h   [NMAX * D];          // GEMM output, fp16, pre-scaled by dinv
__device__ float  g_aggA[NMAX * D];
__device__ float  g_aggB[NMAX * D];
__device__ float  g_x1  [NMAX * D];
__device__ float  g_x2  [NMAX * D];
__device__ float  g_dinv[NMAX];
__device__ int    g_counts[NMAX];
__device__ int    g_rowptr[NMAX + 1];
__device__ int    g_linc[NMAX];
__device__ int    g_bsums[128];
__device__ int    g_wofs[NMAX];
__device__ int    g_col[EMAX];
__device__ float  g_stats[3 * 2 * D];
__device__ float  g_Wcat[D * D];
__device__ float  g_bcat[D];

// ---------------- graph preprocessing ----------------
__global__ void k_count(const int* __restrict__ dst, int* counts, int e) {
    int i = blockIdx.x * blockDim.x + threadIdx.x;
    if (i < e) atomicAdd(&counts[dst[i]], 1);
}

// per-block (1024) inclusive scan; local inclusive -> linc, block total -> bsums
__global__ __launch_bounds__(1024) void k_scan1(const int* __restrict__ counts,
                                                int* linc, int* bsums, int n) {
    __shared__ int ws[32];
    const int tid = threadIdx.x, lane = tid & 31, wid = tid >> 5;
    int i = blockIdx.x * 1024 + tid;
    int v = (i < n) ? counts[i] : 0;
    int s = v;
    #pragma unroll
    for (int off = 1; off < 32; off <<= 1) {
        int t = __shfl_up_sync(0xffffffffu, s, off);
        if (lane >= off) s += t;
    }
    if (lane == 31) ws[wid] = s;
    __syncthreads();
    if (wid == 0) {
        int t2 = ws[lane];
        #pragma unroll
        for (int off = 1; off < 32; off <<= 1) {
            int t = __shfl_up_sync(0xffffffffu, t2, off);
            if (lane >= off) t2 += t;
        }
        ws[lane] = t2;
    }
    __syncthreads();
    int inc = s + (wid ? ws[wid - 1] : 0);
    if (i < n) linc[i] = inc;
    if (tid == 1023) bsums[blockIdx.x] = inc;
}

// single-block exclusive scan of block sums (<=128 entries)
__global__ void k_scan2(int* bsums, int nb) {
    __shared__ int sh[128];
    int tid = threadIdx.x;
    sh[tid] = (tid < nb) ? bsums[tid] : 0;
    __syncthreads();
    #pragma unroll
    for (int off = 1; off < 128; off <<= 1) {
        int t = (tid >= off) ? sh[tid - off] : 0;
        __syncthreads();
        sh[tid] += t;
        __syncthreads();
    }
    if (tid < nb) bsums[tid] = (tid == 0) ? 0 : sh[tid - 1];
}

// finalize rowptr + wofs + dinv + pack head weights
__global__ void k_aux_pack(const int* __restrict__ linc, const int* __restrict__ bsums,
                           const int* __restrict__ counts,
                           int* rowptr, int* wofs, float* dinv,
                           const float* __restrict__ Wmu, const float* __restrict__ Wlv,
                           const float* __restrict__ bmu, const float* __restrict__ blv,
                           float* Wcat, float* bcat, int n) {
    int i = blockIdx.x * blockDim.x + threadIdx.x;
    if (i < n) {
        int rp1 = linc[i] + bsums[i >> 10];
        rowptr[i + 1] = rp1;
        wofs[i] = rp1 - counts[i];
        dinv[i] = rsqrtf((float)(counts[i] + 1));   // +1 self-loop
        if (i == 0) rowptr[0] = 0;
    }
    if (i < D * D) {
        int k = i >> 7, c = i & 127;
        Wcat[i] = (c < LDIM) ? Wmu[k * LDIM + c] : Wlv[k * LDIM + (c - LDIM)];
    }
    if (i < D) bcat[i] = (i < LDIM) ? bmu[i] : blv[i - LDIM];
}

__global__ void k_fill(const int* __restrict__ src, const int* __restrict__ dst,
                       int* wofs, int* col, int e) {
    int i = blockIdx.x * blockDim.x + threadIdx.x;
    if (i < e) {
        int d = dst[i];
        int pos = atomicAdd(&wofs[d], 1);
        col[pos] = src[i];
    }
}

// ---------------- tf32 tensor-core GEMM with 3-term split ----------------
__device__ __forceinline__ uint32_t f2tf(float x) {
    uint32_t r;
    asm("cvt.rna.tf32.f32 %0, %1;" : "=r"(r) : "f"(x));
    return r;
}

__device__ __forceinline__ void mma8(float* d, const uint32_t* a, const uint32_t* b) {
    asm volatile(
        "mma.sync.aligned.m16n8k8.row.col.f32.tf32.tf32.f32 "
        "{%0,%1,%2,%3}, {%4,%5,%6,%7}, {%8,%9}, {%0,%1,%2,%3};"
        : "+f"(d[0]), "+f"(d[1]), "+f"(d[2]), "+f"(d[3])
        : "r"(a[0]), "r"(a[1]), "r"(a[2]), "r"(a[3]), "r"(b[0]), "r"(b[1]));
}

// C_h[M,128] (fp16) = dinv[m] * (A'[M,128] @ B[128,128]); A' = lrelu(BN(A))+xres when FUSE.
template <bool FUSE, bool WRITE_X>
__global__ __launch_bounds__(256) void k_gemm(const float* __restrict__ A,
                                              const float* __restrict__ B,
                                              __half2* __restrict__ C2,
                                              const float* __restrict__ dinv,
                                              const float* __restrict__ stats,
                                              const float* __restrict__ gamma,
                                              const float* __restrict__ beta,
                                              const float* __restrict__ xres,
                                              float* __restrict__ xout, int M) {
    extern __shared__ float sm[];
    float* As = sm;             // 8192: [kt(16)][mt(4)][lane(32)][j(4)]
    float* Bs = sm + 8192;      // 16384: [kt(16)][nt(16)][lane(32)][j(2)]
    float* SC = sm + 24576;     // 128
    float* SF = sm + 24704;     // 128

    const int tid  = threadIdx.x;
    const int lane = tid & 31;
    const int warp = tid >> 5;
    const int wm = warp >> 1;
    const int wn = warp & 1;
    const int row0 = blockIdx.x * 64;

    if (FUSE) {
        if (tid < 128) {
            float inv_n = 1.f / (float)M;
            float mean = stats[tid] * inv_n;
            float var  = stats[128 + tid] * inv_n - mean * mean;
            float s = gamma[tid] * rsqrtf(var + EPS);
            SC[tid] = s;
            SF[tid] = beta[tid] - mean * s;
        }
        __syncthreads();
    }

    #pragma unroll
    for (int i = tid; i < 16384; i += 256) {
        int k = i >> 7, nn = i & 127;
        int kt = k >> 3, ki = k & 7, nt = nn >> 3, ni = nn & 7;
        Bs[((kt * 16 + nt) * 32 + ni * 4 + (ki & 3)) * 2 + (ki >> 2)] = B[i];
    }
    #pragma unroll
    for (int i = tid; i < 8192; i += 256) {
        int m = i >> 7, k = i & 127;
        int gr = row0 + m;
        float v = 0.f;
        if (gr < M) {
            v = A[gr * 128 + k];
            if (FUSE) {
                v = fmaf(v, SC[k], SF[k]);
                v = (v >= 0.f) ? v : SLOPE * v;
                v += xres[gr * 128 + k];
                if (WRITE_X) xout[gr * 128 + k] = v;
            }
        }
        int mt = m >> 4, mi = m & 15, kt = k >> 3, ki = k & 7;
        As[((kt * 4 + mt) * 32 + (mi & 7) * 4 + (ki & 3)) * 4 +
           ((ki >> 2) * 2 + (mi >> 3))] = v;
    }
    __syncthreads();

    float acc[8][4];
    #pragma unroll
    for (int nt = 0; nt < 8; nt++)
        #pragma unroll
        for (int j = 0; j < 4; j++) acc[nt][j] = 0.f;

    #pragma unroll 4
    for (int kt = 0; kt < 16; kt++) {
        float4 av = *(const float4*)&As[((kt * 4 + wm) * 32 + lane) * 4];
        float af[4] = {av.x, av.y, av.z, av.w};
        uint32_t ah[4], al[4];
        #pragma unroll
        for (int j = 0; j < 4; j++) {
            ah[j] = f2tf(af[j]);
            al[j] = f2tf(af[j] - __uint_as_float(ah[j]));
        }
        #pragma unroll
        for (int nt = 0; nt < 8; nt++) {
            float2 bv = *(const float2*)&Bs[((kt * 16 + wn * 8 + nt) * 32 + lane) * 2];
            uint32_t bh[2], bl[2];
            bh[0] = f2tf(bv.x); bl[0] = f2tf(bv.x - __uint_as_float(bh[0]));
            bh[1] = f2tf(bv.y); bl[1] = f2tf(bv.y - __uint_as_float(bh[1]));
            mma8(acc[nt], ah, bh);
            mma8(acc[nt], ah, bl);
            mma8(acc[nt], al, bh);
        }
    }

    const int g = lane >> 2, t = lane & 3;
    const int r0 = row0 + wm * 16 + g;
    const float s0 = (r0 < M)     ? dinv[r0]     : 0.f;
    const float s1 = (r0 + 8 < M) ? dinv[r0 + 8] : 0.f;
    #pragma unroll
    for (int nt = 0; nt < 8; nt++) {
        int c2 = wn * 32 + nt * 4 + t;   // half2 column index
        if (r0 < M)
            C2[r0 * 64 + c2] = __floats2half2_rn(acc[nt][0] * s0, acc[nt][1] * s0);
        if (r0 + 8 < M)
            C2[(r0 + 8) * 64 + c2] = __floats2half2_rn(acc[nt][2] * s1, acc[nt][3] * s1);
    }
}

// ---------------- propagation (+ fused BN statistics) ----------------
__device__ __forceinline__ void acc_add(float4& a, uint2 r) {
    float2 f0 = __half22float2(*reinterpret_cast<__half2*>(&r.x));
    float2 f1 = __half22float2(*reinterpret_cast<__half2*>(&r.y));
    a.x += f0.x; a.y += f0.y; a.z += f1.x; a.w += f1.y;
}

// h (fp16, pre-scaled by dinv): out[d] = dinv[d]*(sum_s h[s] + h[d]) + b.
// 256 threads, 8 warps x 8 nodes = 64 nodes/block.
template <bool SPLIT, bool STATS>
__global__ __launch_bounds__(256) void k_prop(const uint2* __restrict__ hh,
                                              const float* __restrict__ dinv,
                                              const int* __restrict__ rowptr,
                                              const int* __restrict__ col,
                                              const float* __restrict__ bias,
                                              float4* __restrict__ out_a,
                                              float4* __restrict__ out_b,
                                              float* __restrict__ stats, int n) {
    __shared__ float s_red[256];
    const int lane = threadIdx.x & 31;
    const int warp = threadIdx.x >> 5;
    if (STATS) {
        s_red[threadIdx.x] = 0.f;
        __syncthreads();
    }
    const float4 b4 = *(const float4*)(bias + lane * 4);
    float4 ps = make_float4(0.f, 0.f, 0.f, 0.f);
    float4 pq = make_float4(0.f, 0.f, 0.f, 0.f);
    const int base = blockIdx.x * 64 + warp * 8;
    for (int i = 0; i < 8; i++) {
        int w = base + i;
        if (w >= n) break;
        float dd = dinv[w];
        float4 a0 = make_float4(0.f, 0.f, 0.f, 0.f);
        float4 a1 = make_float4(0.f, 0.f, 0.f, 0.f);
        acc_add(a0, hh[w * 32 + lane]);       // self term
        int e = rowptr[w];
        const int end = rowptr[w + 1];
        for (; e + 4 <= end; e += 4) {
            int s0c = col[e], s1c = col[e + 1], s2c = col[e + 2], s3c = col[e + 3];
            uint2 u0 = hh[s0c * 32 + lane];
            uint2 u1 = hh[s1c * 32 + lane];
            uint2 u2 = hh[s2c * 32 + lane];
            uint2 u3 = hh[s3c * 32 + lane];
            acc_add(a0, u0); acc_add(a1, u1);
            acc_add(a0, u2); acc_add(a1, u3);
        }
        for (; e < end; e++) acc_add(a0, hh[col[e] * 32 + lane]);
        float4 acc;
        acc.x = fmaf(a0.x + a1.x, dd, b4.x);
        acc.y = fmaf(a0.y + a1.y, dd, b4.y);
        acc.z = fmaf(a0.z + a1.z, dd, b4.z);
        acc.w = fmaf(a0.w + a1.w, dd, b4.w);
        if (STATS) {
            ps.x += acc.x; ps.y += acc.y; ps.z += acc.z; ps.w += acc.w;
            pq.x += acc.x * acc.x; pq.y += acc.y * acc.y;
            pq.z += acc.z * acc.z; pq.w += acc.w * acc.w;
        }
        if (!SPLIT) {
            out_a[w * 32 + lane] = acc;
        } else {
            if (lane < 16) out_a[w * 16 + lane]        = acc;   // mu
            else           out_b[w * 16 + (lane - 16)] = acc;   // logvar
        }
    }
    if (STATS) {
        atomicAdd(&s_red[lane * 4 + 0], ps.x);
        atomicAdd(&s_red[lane * 4 + 1], ps.y);
        atomicAdd(&s_red[lane * 4 + 2], ps.z);
        atomicAdd(&s_red[lane * 4 + 3], ps.w);
        atomicAdd(&s_red[128 + lane * 4 + 0], pq.x);
        atomicAdd(&s_red[128 + lane * 4 + 1], pq.y);
        atomicAdd(&s_red[128 + lane * 4 + 2], pq.z);
        atomicAdd(&s_red[128 + lane * 4 + 3], pq.w);
        __syncthreads();
        atomicAdd(&stats[threadIdx.x], s_red[threadIdx.x]);
    }
}

// ---------------- launcher ----------------
extern "C" void kernel_launch(void* const* d_in, const int* in_sizes, int n_in,
                              void* d_out, int out_size) {
    const float* x     = (const float*)d_in[0];
    const int*   ei    = (const int*)d_in[1];     // int32 (jax x64 disabled)
    const float* Ws    = (const float*)d_in[2];
    const float* bs    = (const float*)d_in[3];
    const float* Wmu   = (const float*)d_in[4];
    const float* bmu   = (const float*)d_in[5];
    const float* Wlv   = (const float*)d_in[6];
    const float* blv   = (const float*)d_in[7];
    const float* gamma = (const float*)d_in[8];
    const float* beta  = (const float*)d_in[9];

    const int n = in_sizes[0] / D;
    const int e = in_sizes[1] / 2;
    float* out = (float*)d_out;

    __half* h;
    float *aggA, *aggB, *x1, *x2, *dinv, *stats, *Wcat, *bcat;
    int *counts, *rowptr, *linc, *bsums, *wofs, *col;
    cudaGetSymbolAddress((void**)&h,      g_h);
    cudaGetSymbolAddress((void**)&aggA,   g_aggA);
    cudaGetSymbolAddress((void**)&aggB,   g_aggB);
    cudaGetSymbolAddress((void**)&x1,     g_x1);
    cudaGetSymbolAddress((void**)&x2,     g_x2);
    cudaGetSymbolAddress((void**)&dinv,   g_dinv);
    cudaGetSymbolAddress((void**)&stats,  g_stats);
    cudaGetSymbolAddress((void**)&Wcat,   g_Wcat);
    cudaGetSymbolAddress((void**)&bcat,   g_bcat);
    cudaGetSymbolAddress((void**)&counts, g_counts);
    cudaGetSymbolAddress((void**)&rowptr, g_rowptr);
    cudaGetSymbolAddress((void**)&linc,   g_linc);
    cudaGetSymbolAddress((void**)&bsums,  g_bsums);
    cudaGetSymbolAddress((void**)&wofs,   g_wofs);
    cudaGetSymbolAddress((void**)&col,    g_col);

    const int* srcp = ei;
    const int* dstp = ei + e;

    const int SMEM = 24832 * (int)sizeof(float);   // 99328 B
    cudaFuncSetAttribute(k_gemm<false, false>,
                         cudaFuncAttributeMaxDynamicSharedMemorySize, SMEM);
    cudaFuncSetAttribute(k_gemm<true, true>,
                         cudaFuncAttributeMaxDynamicSharedMemorySize, SMEM);
    cudaFuncSetAttribute(k_gemm<true, false>,
                         cudaFuncAttributeMaxDynamicSharedMemorySize, SMEM);

    // preprocessing (proven R4 structure; no cross-block spin anywhere)
    cudaMemsetAsync(counts, 0, (size_t)n * sizeof(int));
    cudaMemsetAsync(stats, 0, 3 * 2 * D * sizeof(float));
    const int nb = (n + 1023) / 1024;
    k_count<<<(e + 255) / 256, 256>>>(dstp, counts, e);
    k_scan1<<<nb, 1024>>>(counts, linc, bsums, n);
    k_scan2<<<1, 128>>>(bsums, nb);
    k_aux_pack<<<(n + 255) / 256, 256>>>(linc, bsums, counts, rowptr, wofs, dinv,
                                         Wmu, Wlv, bmu, blv, Wcat, bcat, n);
    k_fill<<<(e + 255) / 256, 256>>>(srcp, dstp, wofs, col, e);

    const int gemm_grid = (n + 63) / 64;
    const int prop_grid = (n + 63) / 64;

    // layer 0
    k_gemm<false, false><<<gemm_grid, 256, SMEM>>>(x, Ws, (__half2*)h, dinv,
                                                   nullptr, nullptr, nullptr,
                                                   nullptr, nullptr, n);
    k_prop<false, true><<<prop_grid, 256>>>((const uint2*)h, dinv, rowptr, col,
                                            bs, (float4*)aggA, nullptr, stats, n);
    // layer 1 (GEMM applies BN of layer 0)
    k_gemm<true, true><<<gemm_grid, 256, SMEM>>>(aggA, Ws + D * D, (__half2*)h,
                                                 dinv, stats, gamma, beta, x, x1, n);
    k_prop<false, true><<<prop_grid, 256>>>((const uint2*)h, dinv, rowptr, col,
                                            bs + D, (float4*)aggB, nullptr,
                                            stats + 256, n);
    // layer 2 (GEMM applies BN of layer 1)
    k_gemm<true, true><<<gemm_grid, 256, SMEM>>>(aggB, Ws + 2 * D * D, (__half2*)h,
                                                 dinv, stats + 256, gamma, beta,
                                                 x1, x2, n);
    k_prop<false, true><<<prop_grid, 256>>>((const uint2*)h, dinv, rowptr, col,
                                            bs + 2 * D, (float4*)aggA, nullptr,
                                            stats + 512, n);
    // heads (GEMM applies BN of layer 2)
    k_gemm<true, false><<<gemm_grid, 256, SMEM>>>(aggA, Wcat, (__half2*)h, dinv,
                                                  stats + 512, gamma, beta, x2,
                                                  nullptr, n);
    k_prop<true, false><<<prop_grid, 256>>>((const uint2*)h, dinv, rowptr, col,
                                            bcat, (float4*)out,
                                            (float4*)(out + (size_t)n * LDIM),
                                            nullptr, n);
}